// round 3
// baseline (speedup 1.0000x reference)
#include <cuda_runtime.h>
#include <cstdint>
#include <cmath>

// ---------------------------------------------------------------------------
// WeightedRankNet, fused: one big kernel does BOTH the random 5-column gather
// (avg-independent partials -> scratch) AND the column-16 mean partial sums,
// so the strided column walk overlaps the latency-bound random gather.
// Then: tiny finalize (mean) + streaming fixup (combine with avg).
// Threefry-2x32-20, key=(0,1), partitionable counters: bits = out0 ^ out1.
// ---------------------------------------------------------------------------

#define N_FEAT        136
#define COL_DOCLEN    14
#define COL_WHOLE_LEN 16
#define COL_TF        24
#define COL_INLINK    127
#define COL_OUTLINK   128
#define COL_PAGERANK  129

#define TPB   256
#define MAXB  1024
#define SCRATCH_CAP (1 << 20)   // >= BATCH (1e6)

__device__ float  g_partials[MAXB];
__device__ float  g_avg;
__device__ float4 g_scratch[SCRATCH_CAP];   // (A, D, E, P) per element

// ---- Threefry-2x32 ----------------------------------------------------------
__device__ __forceinline__ uint32_t rotl32(uint32_t x, uint32_t r) {
    return __funnelshift_l(x, x, r);
}

__device__ __forceinline__ uint32_t threefry_bits(uint32_t ctr) {
    // key = (0, 1); counter = (0, ctr); output = out0 ^ out1.
    uint32_t x0 = 0u;
    uint32_t x1 = ctr;
    const uint32_t ks0 = 0u, ks1 = 1u, ks2 = 0x1BD11BDBu;
    x0 += ks0; x1 += ks1;
#define TF_R(r) { x0 += x1; x1 = rotl32(x1, (r)); x1 ^= x0; }
    TF_R(13) TF_R(15) TF_R(26) TF_R(6)
    x0 += ks1; x1 += ks2 + 1u;
    TF_R(17) TF_R(29) TF_R(16) TF_R(24)
    x0 += ks2; x1 += ks0 + 2u;
    TF_R(13) TF_R(15) TF_R(26) TF_R(6)
    x0 += ks0; x1 += ks1 + 3u;
    TF_R(17) TF_R(29) TF_R(16) TF_R(24)
    x0 += ks1; x1 += ks2 + 4u;
    TF_R(13) TF_R(15) TF_R(26) TF_R(6)
    x0 += ks2; x1 += ks0 + 5u;
#undef TF_R
    return x0 ^ x1;
}

// ---- fused kernel: gather partials + col16 partial sums ---------------------
__global__ void __launch_bounds__(TPB)
fused_gather_kernel(const int* __restrict__ idxs,
                    const float* __restrict__ gf,
                    const float* __restrict__ s_k1,
                    const float* __restrict__ s_b,
                    const float* __restrict__ s_bw,
                    const float* __restrict__ s_pr,
                    const float* __restrict__ s_in,
                    const float* __restrict__ s_out,
                    const float* __restrict__ s_fr,
                    int batch, int n_docs, float idf)
{
    const int tid      = blockIdx.x * blockDim.x + threadIdx.x;
    const int nthreads = gridDim.x * blockDim.x;

    const float k1  = __ldg(s_k1);
    const float b   = __ldg(s_b);
    const float bw  = __ldg(s_bw);
    const float prw = __ldg(s_pr);
    const float inw = __ldg(s_in);
    const float otw = __ldg(s_out);
    const float frw = __ldg(s_fr);

    // ---------------- gather phase (avg-independent) ----------------
    for (int base = tid * 4; base < batch; base += nthreads * 4) {
        int idx[4];
        const bool full = (base + 3 < batch);
        if (full) {
            int4 iv = *reinterpret_cast<const int4*>(idxs + base);
            idx[0] = iv.x; idx[1] = iv.y; idx[2] = iv.z; idx[3] = iv.w;
        } else {
            #pragma unroll
            for (int k = 0; k < 4; k++)
                idx[k] = (base + k < batch) ? idxs[base + k] : 0;
        }

        float dl[4], tf[4], inl[4], oul[4], pr[4];
        #pragma unroll
        for (int k = 0; k < 4; k++) {
            long long row = (long long)idx[k] * (long long)N_FEAT;
            dl[k]  = __ldg(gf + row + COL_DOCLEN);
            tf[k]  = __ldg(gf + row + COL_TF);
            inl[k] = __ldg(gf + row + COL_INLINK);
            float2 op = __ldg(reinterpret_cast<const float2*>(gf + row + COL_OUTLINK));
            oul[k] = op.x; pr[k] = op.y;
        }

        #pragma unroll
        for (int k = 0; k < 4; k++) {
            int e = base + k;
            if (e >= batch) break;
            uint32_t bits = threefry_bits((uint32_t)e);
            float u = __uint_as_float((bits >> 9) | 0x3f800000u) - 1.0f;
            u = fmaxf(0.0f, u);
            float P = prw * pr[k] + inw * inl[k] + otw * oul[k] + u * frw;
            float A = bw * idf * (tf[k] * (k1 + 1.0f));
            float D = tf[k] + k1 * (1.0f - b);
            float E = k1 * b * dl[k];
            g_scratch[e] = make_float4(A, D, E, P);
        }
    }

    // ---------------- col16 partial-sum phase ----------------
    float s = 0.0f;
    for (long long i = tid; i < n_docs; i += nthreads)
        s += gf[i * N_FEAT + COL_WHOLE_LEN];

    __shared__ float sd[TPB];
    sd[threadIdx.x] = s;
    __syncthreads();
    for (int k = TPB / 2; k > 0; k >>= 1) {
        if (threadIdx.x < k) sd[threadIdx.x] += sd[threadIdx.x + k];
        __syncthreads();
    }
    if (threadIdx.x == 0) g_partials[blockIdx.x] = sd[0];
}

// ---- finalize: fold partials into the mean ----------------------------------
__global__ void finalize_avg_kernel(int nblocks, int n_docs) {
    __shared__ float sd[MAXB];
    float v = (threadIdx.x < nblocks) ? g_partials[threadIdx.x] : 0.0f;
    sd[threadIdx.x] = v;
    __syncthreads();
    for (int k = MAXB / 2; k > 0; k >>= 1) {
        if (threadIdx.x < k) sd[threadIdx.x] += sd[threadIdx.x + k];
        __syncthreads();
    }
    if (threadIdx.x == 0) g_avg = sd[0] / (float)n_docs;
}

// ---- fixup: combine partials with avg, streaming ----------------------------
__global__ void __launch_bounds__(TPB)
fixup_kernel(float* __restrict__ out, int batch) {
    const float avg = g_avg;
    const int tid      = blockIdx.x * blockDim.x + threadIdx.x;
    const int nthreads = gridDim.x * blockDim.x;

    for (int base = tid * 4; base < batch; base += nthreads * 4) {
        if (base + 3 < batch) {
            float4 o;
            float4 s0 = g_scratch[base + 0];
            float4 s1 = g_scratch[base + 1];
            float4 s2 = g_scratch[base + 2];
            float4 s3 = g_scratch[base + 3];
            o.x = s0.w + s0.x / (s0.y + s0.z / avg);
            o.y = s1.w + s1.x / (s1.y + s1.z / avg);
            o.z = s2.w + s2.x / (s2.y + s2.z / avg);
            o.w = s3.w + s3.x / (s3.y + s3.z / avg);
            *reinterpret_cast<float4*>(out + base) = o;
        } else {
            for (int k = 0; k < 4 && base + k < batch; k++) {
                float4 s = g_scratch[base + k];
                out[base + k] = s.w + s.x / (s.y + s.z / avg);
            }
        }
    }
}

// ---------------------------------------------------------------------------
extern "C" void kernel_launch(void* const* d_in, const int* in_sizes, int n_in,
                              void* d_out, int out_size)
{
    const int*   idxs = (const int*)d_in[0];
    const float* gf   = (const float*)d_in[1];
    const float* k1   = (const float*)d_in[2];
    const float* b    = (const float*)d_in[3];
    const float* bw   = (const float*)d_in[4];
    const float* prw  = (const float*)d_in[5];
    const float* inw  = (const float*)d_in[6];
    const float* outw = (const float*)d_in[7];
    const float* frw  = (const float*)d_in[8];
    float* out = (float*)d_out;

    int batch  = in_sizes[0];
    int n_docs = in_sizes[1] / N_FEAT;

    // idf in the reference's exact f32 operation order (num == total):
    float total = (float)n_docs;
    float idf = logf(((total - total) + 0.5f) / (total + 0.5f) + 1.0f);

    int blocks = (batch + TPB * 4 - 1) / (TPB * 4);
    if (blocks > MAXB) blocks = MAXB;

    fused_gather_kernel<<<blocks, TPB>>>(idxs, gf, k1, b, bw, prw, inw, outw,
                                         frw, batch, n_docs, idf);
    finalize_avg_kernel<<<1, MAXB>>>(blocks, n_docs);

    int fblocks = (batch + TPB * 4 - 1) / (TPB * 4);
    fixup_kernel<<<fblocks, TPB>>>(out, batch);
}